// round 14
// baseline (speedup 1.0000x reference)
#include <cuda_runtime.h>
#include <math_constants.h>

#define MAXQ    4096
#define MAXM    100000
#define MARGIN  0.0625f

// Grid over [-4,4]^3, cell 0.25. Clamped binning is 1-Lipschitz, so any mean
// within distance 0.25 of a query lies in the query cell's 27-neighborhood.
// Exact for arbitrary inputs (border cells clamp-extended to infinity in the
// pruning bound).
#define GS      32
#define NC      (GS * GS * GS)     // 32768 = 32 * 1024
#define SCANBLK 32

#define FP_SCALE 17179869184.0     // 2^34

// ---- static device scratch (zero-init at load; invariants restored each run) ----
__device__ float4             g_q[MAXQ];
__device__ int                g_cnt[NC];        // re-zeroed by scan_kernel
__device__ int                g_off[NC + 1];
__device__ int                g_fill[NC];
__device__ float4             g_pts[MAXM];
__device__ unsigned long long g_state[SCANBLK]; // lookback: flag<<62 | value
__device__ unsigned long long g_acc;            // fixed-point loss accumulator
__device__ unsigned int       g_done;           // query ticket

__device__ __forceinline__ int cell1d(float v) {
    int c = (int)floorf((v + 4.0f) * 4.0f);
    return min(max(c, 0), GS - 1);
}
__device__ __forceinline__ int cidx(float x, float y, float z) {
    return (cell1d(z) * GS + cell1d(y)) * GS + cell1d(x);
}

// Per-axis distance from v to cell i's effective region (clamp-extended at borders)
__device__ __forceinline__ float axd(float v, int i) {
    float lo = fmaf(0.25f, (float)i, -4.0f);
    float hi = lo + 0.25f;
    float d = 0.f;
    if (i > 0 && v < lo)           d = lo - v;
    else if (i < GS - 1 && v > hi) d = v - hi;
    return d;
}

// Warp-min of a non-negative float in ONE instruction (bits are monotone for f>=0)
__device__ __forceinline__ float warp_min_pos(float f) {
    return __uint_as_float(__reduce_min_sync(0xFFFFFFFFu, __float_as_uint(f)));
}

// ---------------------------------------------------------------------------
// Kernel 1: reset lookback state + transform queries + count means per cell.
// Means processed 4-per-thread via float4 loads (MLP + fewer threads).
// ---------------------------------------------------------------------------
__global__ void prep_count_kernel(const float* __restrict__ outputs,
                                  const float* __restrict__ c2ws,
                                  const float* __restrict__ scales,
                                  const float* __restrict__ means,
                                  int N, int Qtot, int M) {
    int gid = blockIdx.x * blockDim.x + threadIdx.x;

    if (gid < SCANBLK) g_state[gid] = 0ull;

    if (gid < Qtot) {
        int b = gid / N, n = gid % N;
        float s = scales[b];
        const float* o = outputs + ((size_t)b * N + n) * 3;
        const float* c = c2ws + (size_t)b * 16;
        float ox = o[0], oy = o[1], oz = o[2];
        float qx = fmaf(s, fmaf(ox, c[0], fmaf(oy, c[1], oz * c[2])),  c[3]);
        float qy = fmaf(s, fmaf(ox, c[4], fmaf(oy, c[5], oz * c[6])),  c[7]);
        float qz = fmaf(s, fmaf(ox, c[8], fmaf(oy, c[9], oz * c[10])), c[11]);
        g_q[gid] = make_float4(qx, qy, qz, 0.f);
    }

    int m0 = gid * 4;
    if (m0 + 4 <= M) {
        const float4* p = (const float4*)means + (size_t)gid * 3;
        float4 a = p[0], b = p[1], c = p[2];
        atomicAdd(&g_cnt[cidx(a.x, a.y, a.z)], 1);
        atomicAdd(&g_cnt[cidx(a.w, b.x, b.y)], 1);
        atomicAdd(&g_cnt[cidx(b.z, b.w, c.x)], 1);
        atomicAdd(&g_cnt[cidx(c.y, c.z, c.w)], 1);
    } else if (m0 < M) {
        for (int m = m0; m < M; ++m)
            atomicAdd(&g_cnt[cidx(means[3*m], means[3*m+1], means[3*m+2])], 1);
    }
}

// ---------------------------------------------------------------------------
// Kernel 2: single-kernel ordered exclusive scan (decoupled lookback).
// 32 blocks x 256 threads, 4 cells/thread. All co-resident -> no deadlock.
// Zeroes g_cnt behind itself (restores invariant for next graph replay).
// ---------------------------------------------------------------------------
__global__ void __launch_bounds__(256) scan_kernel() {
    __shared__ int ws_incl[8];
    __shared__ int ws_excl[8];
    __shared__ int sh_prefix;

    const int tid  = threadIdx.x;
    const int bid  = blockIdx.x;
    const int lane = tid & 31;
    const int w    = tid >> 5;
    const int base = bid * 1024 + tid * 4;

    int4 v = *(const int4*)&g_cnt[base];
    int s = v.x + v.y + v.z + v.w;

    int inc = s;
#pragma unroll
    for (int o = 1; o < 32; o <<= 1) {
        int t = __shfl_up_sync(0xFFFFFFFFu, inc, o);
        if (lane >= o) inc += t;
    }
    if (lane == 31) ws_incl[w] = inc;
    __syncthreads();
    if (tid < 8) {
        int e = 0;
#pragma unroll
        for (int k = 0; k < 8; ++k)
            if (k < tid) e += ws_incl[k];
        ws_excl[tid] = e;
    }
    __syncthreads();

    const int block_total = ws_excl[7] + ws_incl[7];
    const int excl = (inc - s) + ws_excl[w];

    if (tid == 0) {
        atomicExch(&g_state[bid], (1ull << 62) | (unsigned long long)block_total);
        unsigned long long prefix = 0;
        for (int i = bid - 1; i >= 0;) {
            unsigned long long st;
            do { st = atomicAdd(&g_state[i], 0ull); } while ((st >> 62) == 0ull);
            prefix += st & 0x3FFFFFFFFFFFFFFFull;
            if ((st >> 62) == 2ull) break;
            --i;
        }
        atomicExch(&g_state[bid],
                   (2ull << 62) | (unsigned long long)(prefix + block_total));
        sh_prefix = (int)prefix;
    }
    __syncthreads();

    const int p = sh_prefix + excl;
    int4 ov = make_int4(p, p + v.x, p + v.x + v.y, p + v.x + v.y + v.z);
    *(int4*)&g_off[base]  = ov;
    *(int4*)&g_fill[base] = ov;
    *(int4*)&g_cnt[base]  = make_int4(0, 0, 0, 0);   // restore zero-invariant

    if (bid == SCANBLK - 1 && tid == 255)
        g_off[NC] = ov.w + v.w;
}

// ---------------------------------------------------------------------------
// Kernel 3: scatter means into cell-sorted order (4 means/thread, float4 loads)
// ---------------------------------------------------------------------------
__global__ void scatter_kernel(const float* __restrict__ means, int M) {
    int gid = blockIdx.x * blockDim.x + threadIdx.x;
    int m0 = gid * 4;
    if (m0 + 4 <= M) {
        const float4* p = (const float4*)means + (size_t)gid * 3;
        float4 a = p[0], b = p[1], c = p[2];
        int p0 = atomicAdd(&g_fill[cidx(a.x, a.y, a.z)], 1);
        g_pts[p0] = make_float4(a.x, a.y, a.z, 0.f);
        int p1 = atomicAdd(&g_fill[cidx(a.w, b.x, b.y)], 1);
        g_pts[p1] = make_float4(a.w, b.x, b.y, 0.f);
        int p2 = atomicAdd(&g_fill[cidx(b.z, b.w, c.x)], 1);
        g_pts[p2] = make_float4(b.z, b.w, c.x, 0.f);
        int p3 = atomicAdd(&g_fill[cidx(c.y, c.z, c.w)], 1);
        g_pts[p3] = make_float4(c.y, c.z, c.w, 0.f);
    } else if (m0 < M) {
        for (int m = m0; m < M; ++m) {
            float x = means[3*m], y = means[3*m+1], z = means[3*m+2];
            int pos = atomicAdd(&g_fill[cidx(x, y, z)], 1);
            g_pts[pos] = make_float4(x, y, z, 0.f);
        }
    }
}

// ---------------------------------------------------------------------------
// Kernel 4: warp-per-query NN, exact pruning, exactly TWO warp reductions
// (REDUX.MIN.U32 each), fused deterministic fixed-point reduction.
//   Phase 1: scan home cell -> reduce -> best (prune bound).
//   Phase 2: prune 26 neighbors vs fixed bound; accumulate per-lane minima
//            over all surviving cells; one final reduce.
// ---------------------------------------------------------------------------
__global__ void __launch_bounds__(256) query_kernel(float* __restrict__ out, int Q) {
    __shared__ float wterm[8];
    const int tid  = threadIdx.x;
    const int lane = tid & 31;
    const int warp = tid >> 5;
    const int qid  = blockIdx.x * 8 + warp;

    float term = 0.f;
    if (qid < Q) {                       // warp-uniform branch
        float4 qv = g_q[qid];
        const int cx = cell1d(qv.x), cy = cell1d(qv.y), cz = cell1d(qv.z);

        // Phase 1: home cell
        float lb = MARGIN;
        {
            const int home = (cz * GS + cy) * GS + cx;
            const int s0 = g_off[home], e0 = g_off[home + 1];
            for (int t = s0 + lane; t < e0; t += 32) {
                float4 m = g_pts[t];
                float dx = qv.x - m.x, dy = qv.y - m.y, dz = qv.z - m.z;
                lb = fminf(lb, fmaf(dx, dx, fmaf(dy, dy, dz * dz)));
            }
        }
        const float bound = warp_min_pos(lb);   // reduction #1

        // Phase 2: pruned neighbors, per-lane accumulation only
        float lb2 = bound;
        if (bound > 0.0f) {
            const int x0 = max(cx - 1, 0), x1 = min(cx + 1, GS - 1);
            const int y0 = max(cy - 1, 0), y1 = min(cy + 1, GS - 1);
            const int z0 = max(cz - 1, 0), z1 = min(cz + 1, GS - 1);

            for (int zi = z0; zi <= z1; ++zi) {
                const float az = axd(qv.z, zi);
                const float az2 = az * az;
                if (az2 >= bound) continue;
                for (int yi = y0; yi <= y1; ++yi) {
                    const float ay = axd(qv.y, yi);
                    const float byz = fmaf(ay, ay, az2);
                    if (byz >= bound) continue;
                    const int row = (zi * GS + yi) * GS;
                    for (int xi = x0; xi <= x1; ++xi) {
                        if (xi == cx && yi == cy && zi == cz) continue;
                        const float ax = axd(qv.x, xi);
                        if (fmaf(ax, ax, byz) >= bound) continue;
                        const int c = row + xi;
                        const int s0 = g_off[c], e0 = g_off[c + 1];
                        for (int t = s0 + lane; t < e0; t += 32) {
                            float4 m = g_pts[t];
                            float dx = qv.x - m.x, dy = qv.y - m.y, dz = qv.z - m.z;
                            lb2 = fminf(lb2, fmaf(dx, dx, fmaf(dy, dy, dz * dz)));
                        }
                    }
                }
            }
        }
        const float best = warp_min_pos(lb2);   // reduction #2
        term = MARGIN - best;                   // in [0, MARGIN]
    }

    if (lane == 0) wterm[warp] = term;
    __syncthreads();

    if (tid == 0) {
        double s = 0.0;
#pragma unroll
        for (int w = 0; w < 8; ++w) s += (double)wterm[w];
        unsigned long long fx = (unsigned long long)__double2ll_rn(s * FP_SCALE);
        atomicAdd(&g_acc, fx);
        __threadfence();
        if (atomicAdd(&g_done, 1u) == gridDim.x - 1) {
            unsigned long long tot = atomicExch(&g_acc, 0ull);
            atomicExch(&g_done, 0u);
            out[0] = (float)(((double)tot / FP_SCALE) / (double)Q);
        }
    }
}

extern "C" void kernel_launch(void* const* d_in, const int* in_sizes, int n_in,
                              void* d_out, int out_size) {
    const float* outputs = (const float*)d_in[0];  // (B, N, 3)
    const float* c2ws    = (const float*)d_in[1];  // (B, 4, 4)
    const float* scales  = (const float*)d_in[2];  // (B,)
    const float* means   = (const float*)d_in[3];  // (M, 3)

    int B = in_sizes[2];
    int Q = in_sizes[0] / 3;              // B*N
    int N = (B > 0) ? (Q / B) : 0;
    int M = in_sizes[3] / 3;
    if (Q > MAXQ) Q = MAXQ;
    if (M > MAXM) M = MAXM;

    int mthreads = (M + 3) / 4;           // 4 means per thread
    int work = mthreads > Q ? mthreads : Q;
    int nb1  = (work + 255) / 256;
    int nbs  = (mthreads + 255) / 256;
    int nqb  = (Q + 7) / 8;

    prep_count_kernel<<<nb1, 256>>>(outputs, c2ws, scales, means, N, Q, M);
    scan_kernel      <<<SCANBLK, 256>>>();
    scatter_kernel   <<<nbs, 256>>>(means, M);
    query_kernel     <<<nqb, 256>>>((float*)d_out, Q);
}

// round 15
// speedup vs baseline: 1.2569x; 1.2569x over previous
#include <cuda_runtime.h>
#include <math_constants.h>

#define MAXQ    4096
#define MAXM    100000
#define MARGIN  0.0625f

// Grid over [-4,4]^3, cell 0.25. Clamped binning is 1-Lipschitz, so any mean
// within distance 0.25 of a query lies in the query cell's 27-neighborhood.
// Exact for arbitrary inputs (border cells clamp-extended to infinity in the
// pruning bound).
#define GS      32
#define NC      (GS * GS * GS)     // 32768 = 32 * 1024
#define SCANBLK 32

#define FP_SCALE 17179869184.0     // 2^34

// ---- static device scratch (zero-init at load; invariants restored each run) ----
__device__ float4             g_q[MAXQ];
__device__ int                g_cnt[NC];        // re-zeroed by scan_kernel
__device__ int                g_off[NC + 1];
__device__ int                g_fill[NC];
__device__ float4             g_pts[MAXM];
__device__ unsigned long long g_state[SCANBLK]; // lookback: flag<<62 | value
__device__ unsigned long long g_acc;            // fixed-point loss accumulator
__device__ unsigned int       g_done;           // query ticket

__device__ __forceinline__ int cell1d(float v) {
    int c = (int)floorf((v + 4.0f) * 4.0f);
    return min(max(c, 0), GS - 1);
}
__device__ __forceinline__ int cidx(float x, float y, float z) {
    return (cell1d(z) * GS + cell1d(y)) * GS + cell1d(x);
}

// Per-axis distance from v to cell i's effective region (clamp-extended at borders)
__device__ __forceinline__ float axd(float v, int i) {
    float lo = fmaf(0.25f, (float)i, -4.0f);
    float hi = lo + 0.25f;
    float d = 0.f;
    if (i > 0 && v < lo)           d = lo - v;
    else if (i < GS - 1 && v > hi) d = v - hi;
    return d;
}

// Warp-min of a non-negative float in ONE instruction (bits monotone for f>=0)
__device__ __forceinline__ float warp_min_pos(float f) {
    return __uint_as_float(__reduce_min_sync(0xFFFFFFFFu, __float_as_uint(f)));
}

// ---------------------------------------------------------------------------
// Kernel 1: reset lookback state + transform queries + count means per cell.
// ---------------------------------------------------------------------------
__global__ void prep_count_kernel(const float* __restrict__ outputs,
                                  const float* __restrict__ c2ws,
                                  const float* __restrict__ scales,
                                  const float* __restrict__ means,
                                  int N, int Qtot, int M) {
    int gid = blockIdx.x * blockDim.x + threadIdx.x;

    if (gid < SCANBLK) g_state[gid] = 0ull;

    if (gid < Qtot) {
        int b = gid / N, n = gid % N;
        float s = scales[b];
        const float* o = outputs + ((size_t)b * N + n) * 3;
        const float* c = c2ws + (size_t)b * 16;
        float ox = o[0], oy = o[1], oz = o[2];
        float qx = fmaf(s, fmaf(ox, c[0], fmaf(oy, c[1], oz * c[2])),  c[3]);
        float qy = fmaf(s, fmaf(ox, c[4], fmaf(oy, c[5], oz * c[6])),  c[7]);
        float qz = fmaf(s, fmaf(ox, c[8], fmaf(oy, c[9], oz * c[10])), c[11]);
        g_q[gid] = make_float4(qx, qy, qz, 0.f);
    }

    int m0 = gid * 4;
    if (m0 + 4 <= M) {
        const float4* p = (const float4*)means + (size_t)gid * 3;
        float4 a = p[0], b = p[1], c = p[2];
        atomicAdd(&g_cnt[cidx(a.x, a.y, a.z)], 1);
        atomicAdd(&g_cnt[cidx(a.w, b.x, b.y)], 1);
        atomicAdd(&g_cnt[cidx(b.z, b.w, c.x)], 1);
        atomicAdd(&g_cnt[cidx(c.y, c.z, c.w)], 1);
    } else if (m0 < M) {
        for (int m = m0; m < M; ++m)
            atomicAdd(&g_cnt[cidx(means[3*m], means[3*m+1], means[3*m+2])], 1);
    }
}

// ---------------------------------------------------------------------------
// Kernel 2: single-kernel ordered exclusive scan (decoupled lookback).
// ---------------------------------------------------------------------------
__global__ void __launch_bounds__(256) scan_kernel() {
    __shared__ int ws_incl[8];
    __shared__ int ws_excl[8];
    __shared__ int sh_prefix;

    const int tid  = threadIdx.x;
    const int bid  = blockIdx.x;
    const int lane = tid & 31;
    const int w    = tid >> 5;
    const int base = bid * 1024 + tid * 4;

    int4 v = *(const int4*)&g_cnt[base];
    int s = v.x + v.y + v.z + v.w;

    int inc = s;
#pragma unroll
    for (int o = 1; o < 32; o <<= 1) {
        int t = __shfl_up_sync(0xFFFFFFFFu, inc, o);
        if (lane >= o) inc += t;
    }
    if (lane == 31) ws_incl[w] = inc;
    __syncthreads();
    if (tid < 8) {
        int e = 0;
#pragma unroll
        for (int k = 0; k < 8; ++k)
            if (k < tid) e += ws_incl[k];
        ws_excl[tid] = e;
    }
    __syncthreads();

    const int block_total = ws_excl[7] + ws_incl[7];
    const int excl = (inc - s) + ws_excl[w];

    if (tid == 0) {
        atomicExch(&g_state[bid], (1ull << 62) | (unsigned long long)block_total);
        unsigned long long prefix = 0;
        for (int i = bid - 1; i >= 0;) {
            unsigned long long st;
            do { st = atomicAdd(&g_state[i], 0ull); } while ((st >> 62) == 0ull);
            prefix += st & 0x3FFFFFFFFFFFFFFFull;
            if ((st >> 62) == 2ull) break;
            --i;
        }
        atomicExch(&g_state[bid],
                   (2ull << 62) | (unsigned long long)(prefix + block_total));
        sh_prefix = (int)prefix;
    }
    __syncthreads();

    const int p = sh_prefix + excl;
    int4 ov = make_int4(p, p + v.x, p + v.x + v.y, p + v.x + v.y + v.z);
    *(int4*)&g_off[base]  = ov;
    *(int4*)&g_fill[base] = ov;
    *(int4*)&g_cnt[base]  = make_int4(0, 0, 0, 0);   // restore zero-invariant

    if (bid == SCANBLK - 1 && tid == 255)
        g_off[NC] = ov.w + v.w;
}

// ---------------------------------------------------------------------------
// Kernel 3: scatter means into cell-sorted order (4 means/thread, float4 loads)
// ---------------------------------------------------------------------------
__global__ void scatter_kernel(const float* __restrict__ means, int M) {
    int gid = blockIdx.x * blockDim.x + threadIdx.x;
    int m0 = gid * 4;
    if (m0 + 4 <= M) {
        const float4* p = (const float4*)means + (size_t)gid * 3;
        float4 a = p[0], b = p[1], c = p[2];
        int p0 = atomicAdd(&g_fill[cidx(a.x, a.y, a.z)], 1);
        g_pts[p0] = make_float4(a.x, a.y, a.z, 0.f);
        int p1 = atomicAdd(&g_fill[cidx(a.w, b.x, b.y)], 1);
        g_pts[p1] = make_float4(a.w, b.x, b.y, 0.f);
        int p2 = atomicAdd(&g_fill[cidx(b.z, b.w, c.x)], 1);
        g_pts[p2] = make_float4(b.z, b.w, c.x, 0.f);
        int p3 = atomicAdd(&g_fill[cidx(c.y, c.z, c.w)], 1);
        g_pts[p3] = make_float4(c.y, c.z, c.w, 0.f);
    } else if (m0 < M) {
        for (int m = m0; m < M; ++m) {
            float x = means[3*m], y = means[3*m+1], z = means[3*m+2];
            int pos = atomicAdd(&g_fill[cidx(x, y, z)], 1);
            g_pts[pos] = make_float4(x, y, z, 0.f);
        }
    }
}

// ---------------------------------------------------------------------------
// Kernel 4: warp-per-query NN, restructured for MLP:
//   * lanes 0-8 prefetch ALL row offsets of the 27-cell neighborhood in
//     parallel (one L2 round-trip) + per-row box-dist byz
//   * home (z,y)-row (3 contiguous cells) scanned as one streaming loop
//     -> REDUX #1 -> bound
//   * remaining 8 rows pruned vs bound (expected ~0-2 survive); survivors
//     x-refined (contiguous) and streamed; REDUX #2 at the very end
// Fused deterministic fixed-point reduction at the tail.
// ---------------------------------------------------------------------------
__global__ void __launch_bounds__(256) query_kernel(float* __restrict__ out, int Q) {
    __shared__ float wterm[8];
    const int tid  = threadIdx.x;
    const int lane = tid & 31;
    const int warp = tid >> 5;
    const int qid  = blockIdx.x * 8 + warp;

    float term = 0.f;
    if (qid < Q) {                          // warp-uniform
        const float4 qv = g_q[qid];
        const int cx = cell1d(qv.x), cy = cell1d(qv.y), cz = cell1d(qv.z);
        const int x0 = max(cx - 1, 0), x1 = min(cx + 1, GS - 1);
        const int nx = x1 - x0 + 1;         // 2 or 3 (uniform)

        // --- parallel row prefetch: lane r in [0,9) owns row (dz,dy) ---
        float byz = CUDART_INF_F;
        int v0 = 0, v1 = 0, v2 = 0, v3 = 0; // g_off[row + x0 + k], k clamped
        if (lane < 9) {
            const int zi = cz + (lane / 3) - 1;
            const int yi = cy + (lane % 3) - 1;
            if (zi >= 0 && zi < GS && yi >= 0 && yi < GS) {
                const float az = axd(qv.z, zi);
                const float ay = axd(qv.y, yi);
                byz = fmaf(ay, ay, az * az);
                const int row = (zi * GS + yi) * GS;
                v0 = g_off[row + x0];
                v1 = g_off[row + min(x0 + 1, x1 + 1)];
                v2 = g_off[row + min(x0 + 2, x1 + 1)];
                v3 = g_off[row + min(x0 + 3, x1 + 1)];
            }
        }

        // uniform selector: offset k of row r (k in [0, nx])
        #define ROWV(k, r) ((k) == 0 ? __shfl_sync(0xFFFFFFFFu, v0, (r)) : \
                            (k) == 1 ? __shfl_sync(0xFFFFFFFFu, v1, (r)) : \
                            (k) == 2 ? __shfl_sync(0xFFFFFFFFu, v2, (r)) : \
                                       __shfl_sync(0xFFFFFFFFu, v3, (r)))

        // --- home row (r = 4): full 3-cell streaming scan ---
        float lb = MARGIN;
        {
            const int s = __shfl_sync(0xFFFFFFFFu, v0, 4);
            int e;
            if (nx == 3)      e = __shfl_sync(0xFFFFFFFFu, v3, 4);
            else if (nx == 2) e = __shfl_sync(0xFFFFFFFFu, v2, 4);
            else              e = __shfl_sync(0xFFFFFFFFu, v1, 4);
            for (int t = s + lane; t < e; t += 32) {
                float4 m = g_pts[t];
                float dx = qv.x - m.x, dy = qv.y - m.y, dz = qv.z - m.z;
                lb = fminf(lb, fmaf(dx, dx, fmaf(dy, dy, dz * dz)));
            }
        }
        const float bound = warp_min_pos(lb);       // REDUX #1

        // --- other rows, pruned against fixed bound ---
        float lb2 = bound;
        if (bound > 0.0f) {
            // x-refinement bounds (uniform): cell cx always survives (ax=0)
            float axm = (cx - 1 >= 0)  ? axd(qv.x, cx - 1) : 0.f;
            float axp = (cx + 1 < GS)  ? axd(qv.x, cx + 1) : 0.f;
            const float axm2 = axm * axm;
            const float axp2 = axp * axp;

#pragma unroll
            for (int r = 0; r < 9; ++r) {
                if (r == 4) continue;
                const float byz_r = __shfl_sync(0xFFFFFFFFu, byz, r);
                if (byz_r >= bound) continue;       // warp-uniform prune

                int xlo = cx, xhi = cx;
                if (cx - 1 >= x0 && axm2 + byz_r < bound) xlo = cx - 1;
                if (cx + 1 <= x1 && axp2 + byz_r < bound) xhi = cx + 1;

                const int klo = xlo - x0;           // uniform in [0,2]
                const int khi = xhi - x0 + 1;       // uniform in [1,3]
                int s, e;
                switch (klo) {
                    case 0: s = __shfl_sync(0xFFFFFFFFu, v0, r); break;
                    case 1: s = __shfl_sync(0xFFFFFFFFu, v1, r); break;
                    default: s = __shfl_sync(0xFFFFFFFFu, v2, r); break;
                }
                switch (khi) {
                    case 1: e = __shfl_sync(0xFFFFFFFFu, v1, r); break;
                    case 2: e = __shfl_sync(0xFFFFFFFFu, v2, r); break;
                    default: e = __shfl_sync(0xFFFFFFFFu, v3, r); break;
                }
                for (int t = s + lane; t < e; t += 32) {
                    float4 m = g_pts[t];
                    float dx = qv.x - m.x, dy = qv.y - m.y, dz = qv.z - m.z;
                    lb2 = fminf(lb2, fmaf(dx, dx, fmaf(dy, dy, dz * dz)));
                }
            }
        }
        const float best = warp_min_pos(lb2);       // REDUX #2
        term = MARGIN - best;                       // in [0, MARGIN]
        #undef ROWV
    }

    if (lane == 0) wterm[warp] = term;
    __syncthreads();

    if (tid == 0) {
        double s = 0.0;
#pragma unroll
        for (int w = 0; w < 8; ++w) s += (double)wterm[w];
        unsigned long long fx = (unsigned long long)__double2ll_rn(s * FP_SCALE);
        atomicAdd(&g_acc, fx);
        __threadfence();
        if (atomicAdd(&g_done, 1u) == gridDim.x - 1) {
            unsigned long long tot = atomicExch(&g_acc, 0ull);
            atomicExch(&g_done, 0u);
            out[0] = (float)(((double)tot / FP_SCALE) / (double)Q);
        }
    }
}

extern "C" void kernel_launch(void* const* d_in, const int* in_sizes, int n_in,
                              void* d_out, int out_size) {
    const float* outputs = (const float*)d_in[0];  // (B, N, 3)
    const float* c2ws    = (const float*)d_in[1];  // (B, 4, 4)
    const float* scales  = (const float*)d_in[2];  // (B,)
    const float* means   = (const float*)d_in[3];  // (M, 3)

    int B = in_sizes[2];
    int Q = in_sizes[0] / 3;              // B*N
    int N = (B > 0) ? (Q / B) : 0;
    int M = in_sizes[3] / 3;
    if (Q > MAXQ) Q = MAXQ;
    if (M > MAXM) M = MAXM;

    int mthreads = (M + 3) / 4;           // 4 means per thread
    int work = mthreads > Q ? mthreads : Q;
    int nb1  = (work + 255) / 256;
    int nbs  = (mthreads + 255) / 256;
    int nqb  = (Q + 7) / 8;

    prep_count_kernel<<<nb1, 256>>>(outputs, c2ws, scales, means, N, Q, M);
    scan_kernel      <<<SCANBLK, 256>>>();
    scatter_kernel   <<<nbs, 256>>>(means, M);
    query_kernel     <<<nqb, 256>>>((float*)d_out, Q);
}